// round 4
// baseline (speedup 1.0000x reference)
#include <cuda_runtime.h>
#include <cstdint>

// Problem dims (fixed by reference)
#define BB 8
#define TT 2048
#define CC 1024
#define DD 64
#define ROWS (BB*TT)      // 16384
#define S_SPLIT 4
#define QB 128            // queries per attention block
#define KT 32             // key tile in smem
#define NEG_BIG  (-1.0e30f)
#define MASK_S   (-3.0e38f)

// Scratch (allocation-free: __device__ globals)
__device__ float g_q[ROWS*DD];
__device__ float g_k[ROWS*DD];
__device__ float g_v[ROWS*DD];
__device__ float g_po[S_SPLIT*ROWS*DD];
__device__ float g_pm[S_SPLIT*ROWS];
__device__ float g_pl[S_SPLIT*ROWS];

typedef unsigned long long u64;

__device__ __forceinline__ u64 pack2(float lo, float hi){
  u64 r; asm("mov.b64 %0,{%1,%2};" : "=l"(r) : "f"(lo), "f"(hi)); return r;
}
__device__ __forceinline__ void unpack2(u64 v, float &lo, float &hi){
  asm("mov.b64 {%0,%1},%2;" : "=f"(lo), "=f"(hi) : "l"(v));
}
__device__ __forceinline__ u64 ffma2(u64 a, u64 b, u64 c){
  u64 d; asm("fma.rn.f32x2 %0,%1,%2,%3;" : "=l"(d) : "l"(a), "l"(b), "l"(c)); return d;
}
__device__ __forceinline__ u64 fmul2(u64 a, u64 b){
  u64 d; asm("mul.rn.f32x2 %0,%1,%2;" : "=l"(d) : "l"(a), "l"(b)); return d;
}
__device__ __forceinline__ u64 fadd2(u64 a, u64 b){
  u64 d; asm("add.rn.f32x2 %0,%1,%2;" : "=l"(d) : "l"(a), "l"(b)); return d;
}
__device__ __forceinline__ void cpasync16(void* s, const void* g){
  uint32_t sa = (uint32_t)__cvta_generic_to_shared(s);
  asm volatile("cp.async.cg.shared.global [%0], [%1], 16;\n" :: "r"(sa), "l"(g) : "memory");
}
__device__ __forceinline__ void cp_commit(){ asm volatile("cp.async.commit_group;\n" ::: "memory"); }
__device__ __forceinline__ void cp_wait0(){ asm volatile("cp.async.wait_group 0;\n" ::: "memory"); }

// ---------------------------------------------------------------------------
// Kernel 1: fused QKV projection. grid = (ROWS/128, 3), 256 threads.
// BM=128, BN=64, BK=16. x tile stored PRE-DUPLICATED as f32x2 pairs so the
// accumulators pair over COLUMNS (W pairs come free from an LDS.128).
// Register-prefetch double buffering: one barrier per K-tile.
// ---------------------------------------------------------------------------
#define PBK 16
#define PNIT (CC/PBK)   // 64

__global__ __launch_bounds__(256) void proj_kernel(
    const float* __restrict__ x,
    const float* __restrict__ Wk,
    const float* __restrict__ Wq,
    const float* __restrict__ Wv)
{
  __shared__ u64   xs2[2][PBK][128];   // duplicated x vals, [k][row] : 32KB
  __shared__ float ws [2][PBK][DD];    // W tile [k][col]             : 8KB

  const float* W   = (blockIdx.y == 0) ? Wk : ((blockIdx.y == 1) ? Wq : Wv);
  float*       out = (blockIdx.y == 0) ? g_k : ((blockIdx.y == 1) ? g_q : g_v);

  const int rowBase = blockIdx.x * 128;
  const int t  = threadIdx.x;
  const int ty = t >> 4;     // 0..15 -> rows ty*8 .. ty*8+7
  const int tx = t & 15;     // 0..15 -> cols tx*4 .. tx*4+3

  // load indices (fixed per thread)
  const int xr0 = t >> 2;                 // row for load 0 (0..63)
  const int xkc = (t & 3) << 2;           // k offset 0,4,8,12
  const int wrow = t >> 4;                // 0..15
  const int wc   = (t & 15) << 2;         // 0..60

  u64 acc[8][2];
  #pragma unroll
  for (int r = 0; r < 8; r++) { acc[r][0] = pack2(0.f,0.f); acc[r][1] = pack2(0.f,0.f); }

  // prefetch registers
  float4 xA, xB, wA;

  // prologue: load tile 0 into regs, store to stage 0
  {
    const float* xb = x + (size_t)rowBase * CC;        // k0 = 0
    xA = *(const float4*)(xb + (size_t)xr0 * CC + xkc);
    xB = *(const float4*)(xb + (size_t)(xr0 + 64) * CC + xkc);
    wA = *(const float4*)(W + (size_t)wrow * DD + wc);
    xs2[0][xkc+0][xr0] = pack2(xA.x, xA.x);
    xs2[0][xkc+1][xr0] = pack2(xA.y, xA.y);
    xs2[0][xkc+2][xr0] = pack2(xA.z, xA.z);
    xs2[0][xkc+3][xr0] = pack2(xA.w, xA.w);
    xs2[0][xkc+0][xr0+64] = pack2(xB.x, xB.x);
    xs2[0][xkc+1][xr0+64] = pack2(xB.y, xB.y);
    xs2[0][xkc+2][xr0+64] = pack2(xB.z, xB.z);
    xs2[0][xkc+3][xr0+64] = pack2(xB.w, xB.w);
    *(float4*)&ws[0][wrow][wc] = wA;
  }

  for (int it = 0; it < PNIT; it++) {
    const int cur = it & 1;
    const bool hasNext = (it + 1 < PNIT);
    if (hasNext) {
      const int k0 = (it + 1) * PBK;
      const float* xb = x + (size_t)rowBase * CC + k0;
      xA = *(const float4*)(xb + (size_t)xr0 * CC + xkc);
      xB = *(const float4*)(xb + (size_t)(xr0 + 64) * CC + xkc);
      wA = *(const float4*)(W + (size_t)(k0 + wrow) * DD + wc);
    }
    __syncthreads();   // stage[cur] fully stored

    #pragma unroll 4
    for (int kk = 0; kk < PBK; kk++) {
      const ulonglong2* ap = (const ulonglong2*)&xs2[cur][kk][ty * 8];
      ulonglong2 a0 = ap[0], a1 = ap[1], a2 = ap[2], a3 = ap[3];
      float4 b4 = *(const float4*)&ws[cur][kk][tx * 4];
      u64 b01 = pack2(b4.x, b4.y);
      u64 b23 = pack2(b4.z, b4.w);
      u64 ar[8] = { a0.x, a0.y, a1.x, a1.y, a2.x, a2.y, a3.x, a3.y };
      #pragma unroll
      for (int r = 0; r < 8; r++) {
        acc[r][0] = ffma2(ar[r], b01, acc[r][0]);
        acc[r][1] = ffma2(ar[r], b23, acc[r][1]);
      }
    }

    if (hasNext) {
      const int nxt = cur ^ 1;
      xs2[nxt][xkc+0][xr0] = pack2(xA.x, xA.x);
      xs2[nxt][xkc+1][xr0] = pack2(xA.y, xA.y);
      xs2[nxt][xkc+2][xr0] = pack2(xA.z, xA.z);
      xs2[nxt][xkc+3][xr0] = pack2(xA.w, xA.w);
      xs2[nxt][xkc+0][xr0+64] = pack2(xB.x, xB.x);
      xs2[nxt][xkc+1][xr0+64] = pack2(xB.y, xB.y);
      xs2[nxt][xkc+2][xr0+64] = pack2(xB.z, xB.z);
      xs2[nxt][xkc+3][xr0+64] = pack2(xB.w, xB.w);
      *(float4*)&ws[nxt][wrow][wc] = wA;
    }
  }

  // epilogue: 8 rows x 4 contiguous cols per thread
  #pragma unroll
  for (int r = 0; r < 8; r++) {
    float c0, c1, c2, c3;
    unpack2(acc[r][0], c0, c1);
    unpack2(acc[r][1], c2, c3);
    *(float4*)(out + (size_t)(rowBase + ty * 8 + r) * DD + tx * 4) =
        make_float4(c0, c1, c2, c3);
  }
}

// ---------------------------------------------------------------------------
// Kernel 2: flash attention, D-split-2 (two lanes per query), 2-key unroll,
// cp.async double-buffered K/V tiles, uniform causal masking.
// grid = (TT/QB, BB, S_SPLIT), 256 threads (= 128 queries x 2 half-lanes).
// ---------------------------------------------------------------------------
__global__ __launch_bounds__(256) void attn_kernel()
{
  __shared__ float ks[2][KT * DD];   // 16KB
  __shared__ float vs[2][KT * DD];   // 16KB

  const int qb  = blockIdx.x;
  const int b   = blockIdx.y;
  const int sp  = blockIdx.z;
  const int tid = threadIdx.x;
  const int qi   = tid >> 1;          // 0..127 query within block
  const int half = tid & 1;           // which 32 of D this lane owns

  const int t   = qb * QB + qi;       // query position
  const int row = b * TT + t;

  const int ntiles = qb + 1;          // tiles per split
  const int ks0 = sp * ntiles * KT;

  // issue cp.async for one K/V tile (2 x 16B per array per thread)
  auto issue_tile = [&](int it, int stage) {
    const int kt = ks0 + it * KT;
    #pragma unroll
    for (int r = 0; r < 2; r++) {
      int idx = tid + r * 256;          // 0..511
      int kr  = idx >> 4;               // 0..31
      int kc  = (idx & 15) << 2;        // 0..60
      size_t g = ((size_t)(b * TT + kt + kr)) * DD + kc;
      cpasync16(&ks[stage][kr * DD + kc], g_k + g);
      cpasync16(&vs[stage][kr * DD + kc], g_v + g);
    }
    cp_commit();
  };

  issue_tile(0, 0);

  // this lane's half of q, pre-scaled by d^-0.5
  u64 q2[16];
  {
    const float* qp = g_q + (size_t)row * DD + half * 32;
    #pragma unroll
    for (int i = 0; i < 8; i++) {
      float4 v4 = *(const float4*)(qp + i * 4);
      q2[2 * i]     = pack2(v4.x * 0.125f, v4.y * 0.125f);
      q2[2 * i + 1] = pack2(v4.z * 0.125f, v4.w * 0.125f);
    }
  }

  u64 o2[16];
  #pragma unroll
  for (int i = 0; i < 16; i++) o2[i] = pack2(0.f, 0.f);
  float m = NEG_BIG;
  float l = 0.f;

  for (int it = 0; it < ntiles; it++) {
    const int cur = it & 1;
    cp_wait0();
    __syncthreads();
    if (it + 1 < ntiles) issue_tile(it + 1, cur ^ 1);

    const int kt = ks0 + it * KT;
    const float* kbase = &ks[cur][0];
    const float* vbase = &vs[cur][0];

    #pragma unroll 1
    for (int jj = 0; jj < KT; jj += 2) {
      // two independent half-dots
      const ulonglong2* k0p = (const ulonglong2*)(kbase + jj * DD + half * 32);
      const ulonglong2* k1p = (const ulonglong2*)(kbase + (jj + 1) * DD + half * 32);
      u64 z = pack2(0.f, 0.f);
      u64 a0 = z, a1 = z, a2 = z, a3 = z;
      u64 c0 = z, c1 = z, c2c = z, c3 = z;
      #pragma unroll
      for (int i = 0; i < 4; i++) {
        ulonglong2 kuA = k0p[2 * i];
        ulonglong2 kuB = k0p[2 * i + 1];
        a0 = ffma2(q2[4 * i + 0], kuA.x, a0);
        a1 = ffma2(q2[4 * i + 1], kuA.y, a1);
        a2 = ffma2(q2[4 * i + 2], kuB.x, a2);
        a3 = ffma2(q2[4 * i + 3], kuB.y, a3);
        ulonglong2 kvA = k1p[2 * i];
        ulonglong2 kvB = k1p[2 * i + 1];
        c0  = ffma2(q2[4 * i + 0], kvA.x, c0);
        c1  = ffma2(q2[4 * i + 1], kvA.y, c1);
        c2c = ffma2(q2[4 * i + 2], kvB.x, c2c);
        c3  = ffma2(q2[4 * i + 3], kvB.y, c3);
      }
      u64 ra = fadd2(fadd2(a0, a1), fadd2(a2, a3));
      u64 rc = fadd2(fadd2(c0, c1), fadd2(c2c, c3));
      float alo, ahi, clo, chi;
      unpack2(ra, alo, ahi);
      unpack2(rc, clo, chi);
      float sh0 = alo + ahi;
      float sh1 = clo + chi;
      float s0 = sh0 + __shfl_xor_sync(0xffffffffu, sh0, 1);
      float s1 = sh1 + __shfl_xor_sync(0xffffffffu, sh1, 1);
      s0 = (kt + jj     <= t) ? s0 : MASK_S;
      s1 = (kt + jj + 1 <= t) ? s1 : MASK_S;

      // online softmax (shared rescale for the key pair)
      float mn = fmaxf(m, fmaxf(s0, s1));
      float p0 = __expf(s0 - mn);
      float p1 = __expf(s1 - mn);
      if (mn > m) {
        float corr = __expf(m - mn);
        l *= corr;
        u64 cr = pack2(corr, corr);
        #pragma unroll
        for (int i = 0; i < 16; i++) o2[i] = fmul2(o2[i], cr);
      }
      m = mn;
      l += p0 + p1;

      u64 p02 = pack2(p0, p0);
      u64 p12 = pack2(p1, p1);
      const ulonglong2* v0p = (const ulonglong2*)(vbase + jj * DD + half * 32);
      const ulonglong2* v1p = (const ulonglong2*)(vbase + (jj + 1) * DD + half * 32);
      #pragma unroll
      for (int i = 0; i < 8; i++) {
        ulonglong2 va = v0p[i];
        ulonglong2 vb = v1p[i];
        o2[2 * i]     = ffma2(p02, va.x, ffma2(p12, vb.x, o2[2 * i]));
        o2[2 * i + 1] = ffma2(p02, va.y, ffma2(p12, vb.y, o2[2 * i + 1]));
      }
    }
  }

  // write partials (unnormalized)
  size_t pr = (size_t)sp * ROWS + row;
  if (half == 0) { g_pm[pr] = m; g_pl[pr] = l; }
  float* po = g_po + pr * (size_t)DD + half * 32;
  #pragma unroll
  for (int i = 0; i < 8; i++) {
    *(ulonglong2*)(po + 4 * i) = make_ulonglong2(o2[2 * i], o2[2 * i + 1]);
  }
}

// ---------------------------------------------------------------------------
// Kernel 3: LSE combine across splits + final normalization.
// ---------------------------------------------------------------------------
__global__ __launch_bounds__(256) void combine_kernel(float* __restrict__ out)
{
  int r = blockIdx.x * blockDim.x + threadIdx.x;

  float m[S_SPLIT], l[S_SPLIT];
  #pragma unroll
  for (int s = 0; s < S_SPLIT; s++) {
    m[s] = g_pm[(size_t)s * ROWS + r];
    l[s] = g_pl[(size_t)s * ROWS + r];
  }
  float M = fmaxf(fmaxf(m[0], m[1]), fmaxf(m[2], m[3]));
  float w[S_SPLIT]; float L = 0.f;
  #pragma unroll
  for (int s = 0; s < S_SPLIT; s++) { w[s] = __expf(m[s] - M); L += l[s] * w[s]; }
  float inv = 1.0f / L;

  #pragma unroll
  for (int i = 0; i < 16; i++) {
    float4 acc = make_float4(0.f, 0.f, 0.f, 0.f);
    #pragma unroll
    for (int s = 0; s < S_SPLIT; s++) {
      float4 p = *(const float4*)(g_po + ((size_t)s * ROWS + r) * DD + i * 4);
      acc.x += p.x * w[s]; acc.y += p.y * w[s];
      acc.z += p.z * w[s]; acc.w += p.w * w[s];
    }
    acc.x *= inv; acc.y *= inv; acc.z *= inv; acc.w *= inv;
    *(float4*)(out + (size_t)r * DD + i * 4) = acc;
  }
}

// ---------------------------------------------------------------------------
extern "C" void kernel_launch(void* const* d_in, const int* in_sizes, int n_in,
                              void* d_out, int out_size)
{
  const float* x  = (const float*)d_in[0];
  const float* Wk = (const float*)d_in[1];
  const float* Wq = (const float*)d_in[2];
  const float* Wv = (const float*)d_in[3];
  float* out = (float*)d_out;

  proj_kernel<<<dim3(ROWS / 128, 3), 256>>>(x, Wk, Wq, Wv);
  attn_kernel<<<dim3(TT / QB, BB, S_SPLIT), 256>>>();
  combine_kernel<<<ROWS / 256, 256>>>(out);
}

// round 5
// speedup vs baseline: 1.6659x; 1.6659x over previous
#include <cuda_runtime.h>
#include <cstdint>

// Problem dims (fixed by reference)
#define BB 8
#define TT 2048
#define CC 1024
#define DD 64
#define ROWS (BB*TT)      // 16384
#define S_SPLIT 4
#define QB 128            // queries per attention block
#define KT 32             // key tile in smem
#define NEG_BIG  (-1.0e30f)
#define MASK_S   (-3.0e38f)

// Scratch (allocation-free: __device__ globals)
__device__ float g_q[ROWS*DD];
__device__ float g_k[ROWS*DD];
__device__ float g_v[ROWS*DD];
__device__ float g_po[S_SPLIT*ROWS*DD];
__device__ float g_pm[S_SPLIT*ROWS];
__device__ float g_pl[S_SPLIT*ROWS];

typedef unsigned long long u64;

__device__ __forceinline__ u64 pack2(float lo, float hi){
  u64 r; asm("mov.b64 %0,{%1,%2};" : "=l"(r) : "f"(lo), "f"(hi)); return r;
}
__device__ __forceinline__ void unpack2(u64 v, float &lo, float &hi){
  asm("mov.b64 {%0,%1},%2;" : "=f"(lo), "=f"(hi) : "l"(v));
}
__device__ __forceinline__ u64 ffma2(u64 a, u64 b, u64 c){
  u64 d; asm("fma.rn.f32x2 %0,%1,%2,%3;" : "=l"(d) : "l"(a), "l"(b), "l"(c)); return d;
}
__device__ __forceinline__ u64 fmul2(u64 a, u64 b){
  u64 d; asm("mul.rn.f32x2 %0,%1,%2;" : "=l"(d) : "l"(a), "l"(b)); return d;
}
__device__ __forceinline__ u64 fadd2(u64 a, u64 b){
  u64 d; asm("add.rn.f32x2 %0,%1,%2;" : "=l"(d) : "l"(a), "l"(b)); return d;
}
__device__ __forceinline__ void cpasync16(void* s, const void* g){
  uint32_t sa = (uint32_t)__cvta_generic_to_shared(s);
  asm volatile("cp.async.cg.shared.global [%0], [%1], 16;\n" :: "r"(sa), "l"(g) : "memory");
}
__device__ __forceinline__ void cp_commit(){ asm volatile("cp.async.commit_group;\n" ::: "memory"); }
__device__ __forceinline__ void cp_wait0(){ asm volatile("cp.async.wait_group 0;\n" ::: "memory"); }

// ---------------------------------------------------------------------------
// Kernel 1: QKV projection. grid = (128, 3), 128 threads.
// BM=128, BN=64, BK=16. 8x8 microtile per thread (f32x2 paired over cols,
// col set = {tx*4..+3, tx*4+32..+35}). xs transposed [k][row], plain floats.
// Per kk: 4x LDS.128 (64B) for 32 FFMA2 -> 2B/FFMA2 = crossbar-balanced.
// All LDS conflict-free. Double-buffered, reg-prefetch, 1 barrier/tile.
// ---------------------------------------------------------------------------
#define PBK 16
#define PNIT (CC/PBK)   // 64

__global__ __launch_bounds__(128) void proj_kernel(
    const float* __restrict__ x,
    const float* __restrict__ Wk,
    const float* __restrict__ Wq,
    const float* __restrict__ Wv)
{
  __shared__ float xs[2][PBK][128];   // transposed x tile [k][row] : 16KB
  __shared__ float ws[2][PBK][DD];    // W tile [k][col]            : 8KB

  const float* W   = (blockIdx.y == 0) ? Wk : ((blockIdx.y == 1) ? Wq : Wv);
  float*       out = (blockIdx.y == 0) ? g_k : ((blockIdx.y == 1) ? g_q : g_v);

  const int rowBase = blockIdx.x * 128;
  const int t  = threadIdx.x;
  const int tx = t & 7;      // col group: cols tx*4..+3 and tx*4+32..+35
  const int ty = t >> 3;     // 0..15 -> rows ty*8..ty*8+7

  // x load: thread covers rows (t>>2)+32i, k-chunk (t&3)*4
  const int xr  = t >> 2;
  const int xkc = (t & 3) << 2;
  // W load: 2 chunks of 4 floats; chunk id = 2t+j
  const int wr0 = (2 * t)     >> 4, wc0 = ((2 * t)     & 15) << 2;
  const int wr1 = (2 * t + 1) >> 4, wc1 = ((2 * t + 1) & 15) << 2;

  float4 xreg[4];
  float4 wreg[2];

  auto load_tile = [&](int k0) {
    #pragma unroll
    for (int i = 0; i < 4; i++)
      xreg[i] = *(const float4*)(x + (size_t)(rowBase + xr + 32 * i) * CC + k0 + xkc);
    wreg[0] = *(const float4*)(W + (size_t)(k0 + wr0) * DD + wc0);
    wreg[1] = *(const float4*)(W + (size_t)(k0 + wr1) * DD + wc1);
  };
  auto store_tile = [&](int st) {
    #pragma unroll
    for (int i = 0; i < 4; i++) {
      int row = xr + 32 * i;
      xs[st][xkc + 0][row] = xreg[i].x;
      xs[st][xkc + 1][row] = xreg[i].y;
      xs[st][xkc + 2][row] = xreg[i].z;
      xs[st][xkc + 3][row] = xreg[i].w;
    }
    *(float4*)&ws[st][wr0][wc0] = wreg[0];
    *(float4*)&ws[st][wr1][wc1] = wreg[1];
  };

  u64 acc[8][4];
  #pragma unroll
  for (int r = 0; r < 8; r++)
    #pragma unroll
    for (int c = 0; c < 4; c++) acc[r][c] = pack2(0.f, 0.f);

  load_tile(0);
  store_tile(0);

  for (int it = 0; it < PNIT; it++) {
    const int cur = it & 1;
    const bool hasNext = (it + 1 < PNIT);
    if (hasNext) load_tile((it + 1) * PBK);
    __syncthreads();   // stage[cur] complete; all threads done with stage[cur^1]

    #pragma unroll 4
    for (int kk = 0; kk < PBK; kk++) {
      // a: 8 row values (2x LDS.128, conflict-free: ty*8 banks distinct per warp)
      ulonglong2 aA = *(const ulonglong2*)&xs[cur][kk][ty * 8];
      ulonglong2 aB = *(const ulonglong2*)&xs[cur][kk][ty * 8 + 4];
      // b: col pairs (2x LDS.128, banks tx*4 mod 32 distinct)
      ulonglong2 bl = *(const ulonglong2*)&ws[cur][kk][tx * 4];
      ulonglong2 bh = *(const ulonglong2*)&ws[cur][kk][tx * 4 + 32];
      float a[8];
      unpack2(aA.x, a[0], a[1]);
      unpack2(aA.y, a[2], a[3]);
      unpack2(aB.x, a[4], a[5]);
      unpack2(aB.y, a[6], a[7]);
      #pragma unroll
      for (int r = 0; r < 8; r++) {
        u64 ar = pack2(a[r], a[r]);
        acc[r][0] = ffma2(ar, bl.x, acc[r][0]);
        acc[r][1] = ffma2(ar, bl.y, acc[r][1]);
        acc[r][2] = ffma2(ar, bh.x, acc[r][2]);
        acc[r][3] = ffma2(ar, bh.y, acc[r][3]);
      }
    }

    if (hasNext) store_tile(cur ^ 1);
  }

  // epilogue: 8 rows x (4 + 4) cols
  #pragma unroll
  for (int r = 0; r < 8; r++) {
    float c0, c1, c2, c3, c4, c5, c6, c7;
    unpack2(acc[r][0], c0, c1);
    unpack2(acc[r][1], c2, c3);
    unpack2(acc[r][2], c4, c5);
    unpack2(acc[r][3], c6, c7);
    float* op = out + (size_t)(rowBase + ty * 8 + r) * DD;
    *(float4*)(op + tx * 4)      = make_float4(c0, c1, c2, c3);
    *(float4*)(op + tx * 4 + 32) = make_float4(c4, c5, c6, c7);
  }
}

// ---------------------------------------------------------------------------
// Kernel 2: flash attention. D-split-2 with INTERLEAVED half ownership:
// half h owns 16B chunks {2i+h} (floats 8i+4h..+3) -> conflict-free K/V LDS.
// Bulk softmax per 16-key subtile: 16 independent dots, one rescale.
// cp.async double-buffered tiles. grid = (TT/QB, BB, S_SPLIT), 256 threads.
// ---------------------------------------------------------------------------
__global__ __launch_bounds__(256, 2) void attn_kernel()
{
  __shared__ float ks[2][KT * DD];   // 16KB
  __shared__ float vs[2][KT * DD];   // 16KB

  const int qb  = blockIdx.x;
  const int b   = blockIdx.y;
  const int sp  = blockIdx.z;
  const int tid = threadIdx.x;
  const int qi   = tid >> 1;          // 0..127 query within block
  const int half = tid & 1;

  const int t   = qb * QB + qi;       // query position
  const int row = b * TT + t;

  const int ntiles = qb + 1;          // KT-tiles per split
  const int ks0 = sp * ntiles * KT;

  auto issue_tile = [&](int it, int stage) {
    const int kt = ks0 + it * KT;
    #pragma unroll
    for (int r = 0; r < 2; r++) {
      int idx = tid + r * 256;          // 0..511
      int kr  = idx >> 4;               // 0..31
      int kc  = (idx & 15) << 2;        // 0..60
      size_t g = ((size_t)(b * TT + kt + kr)) * DD + kc;
      cpasync16(&ks[stage][kr * DD + kc], g_k + g);
      cpasync16(&vs[stage][kr * DD + kc], g_v + g);
    }
    cp_commit();
  };

  issue_tile(0, 0);

  // this half's 32 floats of q (chunks 2i+half), pre-scaled by d^-0.5
  u64 q2[16];
  {
    const float* qp = g_q + (size_t)row * DD + 4 * half;
    #pragma unroll
    for (int i = 0; i < 8; i++) {
      float4 v4 = *(const float4*)(qp + 8 * i);
      q2[2 * i]     = pack2(v4.x * 0.125f, v4.y * 0.125f);
      q2[2 * i + 1] = pack2(v4.z * 0.125f, v4.w * 0.125f);
    }
  }

  u64 o2[16];
  #pragma unroll
  for (int i = 0; i < 16; i++) o2[i] = pack2(0.f, 0.f);
  float m = NEG_BIG;
  float l = 0.f;

  for (int it = 0; it < ntiles; it++) {
    const int cur = it & 1;
    cp_wait0();
    __syncthreads();
    if (it + 1 < ntiles) issue_tile(it + 1, cur ^ 1);

    const int kt = ks0 + it * KT;
    const float* kbase = &ks[cur][0];
    const float* vbase = &vs[cur][0];

    #pragma unroll
    for (int j0 = 0; j0 < KT; j0 += 16) {
      if (kt + j0 > t) continue;   // subtile fully masked for this query

      // ---- 16 independent half-dots -> full scores via shfl ----
      float s[16];
      #pragma unroll
      for (int j = 0; j < 16; j++) {
        const ulonglong2* kp =
            (const ulonglong2*)(kbase + (j0 + j) * DD + 4 * half);
        u64 z = pack2(0.f, 0.f);
        u64 d0 = z, d1 = z, d2 = z, d3 = z;
        #pragma unroll
        for (int i = 0; i < 8; i += 2) {
          ulonglong2 kcA = kp[2 * i];        // chunk i
          ulonglong2 kcB = kp[2 * i + 2];    // chunk i+1
          d0 = ffma2(q2[2 * i],     kcA.x, d0);
          d1 = ffma2(q2[2 * i + 1], kcA.y, d1);
          d2 = ffma2(q2[2 * i + 2], kcB.x, d2);
          d3 = ffma2(q2[2 * i + 3], kcB.y, d3);
        }
        u64 rr = fadd2(fadd2(d0, d2), fadd2(d1, d3));
        float lo, hi; unpack2(rr, lo, hi);
        float sh = lo + hi;
        float sf = sh + __shfl_xor_sync(0xffffffffu, sh, 1);
        s[j] = (kt + j0 + j <= t) ? sf : MASK_S;
      }

      // ---- subtile max + single branchless rescale ----
      float M = s[0];
      #pragma unroll
      for (int j = 1; j < 16; j++) M = fmaxf(M, s[j]);
      float mn = fmaxf(m, M);
      float corr = __expf(m - mn);
      l *= corr;
      u64 cr = pack2(corr, corr);
      #pragma unroll
      for (int i = 0; i < 16; i++) o2[i] = fmul2(o2[i], cr);
      m = mn;

      // ---- exp + V accumulation ----
      float lsum = 0.f;
      #pragma unroll
      for (int j = 0; j < 16; j++) {
        float p = __expf(s[j] - m);
        lsum += p;
        u64 p2 = pack2(p, p);
        const ulonglong2* vp =
            (const ulonglong2*)(vbase + (j0 + j) * DD + 4 * half);
        #pragma unroll
        for (int i = 0; i < 8; i++) {
          ulonglong2 vv = vp[2 * i];
          o2[2 * i]     = ffma2(p2, vv.x, o2[2 * i]);
          o2[2 * i + 1] = ffma2(p2, vv.y, o2[2 * i + 1]);
        }
      }
      l += lsum;
    }
  }

  // write partials (unnormalized) at this half's interleaved positions
  size_t pr = (size_t)sp * ROWS + row;
  if (half == 0) { g_pm[pr] = m; g_pl[pr] = l; }
  float* po = g_po + pr * (size_t)DD + 4 * half;
  #pragma unroll
  for (int i = 0; i < 8; i++) {
    *(ulonglong2*)(po + 8 * i) = make_ulonglong2(o2[2 * i], o2[2 * i + 1]);
  }
}

// ---------------------------------------------------------------------------
// Kernel 3: LSE combine across splits + final normalization.
// ---------------------------------------------------------------------------
__global__ __launch_bounds__(256) void combine_kernel(float* __restrict__ out)
{
  int r = blockIdx.x * blockDim.x + threadIdx.x;

  float m[S_SPLIT], l[S_SPLIT];
  #pragma unroll
  for (int s = 0; s < S_SPLIT; s++) {
    m[s] = g_pm[(size_t)s * ROWS + r];
    l[s] = g_pl[(size_t)s * ROWS + r];
  }
  float M = fmaxf(fmaxf(m[0], m[1]), fmaxf(m[2], m[3]));
  float w[S_SPLIT]; float L = 0.f;
  #pragma unroll
  for (int s = 0; s < S_SPLIT; s++) { w[s] = __expf(m[s] - M); L += l[s] * w[s]; }
  float inv = 1.0f / L;

  #pragma unroll
  for (int i = 0; i < 16; i++) {
    float4 acc = make_float4(0.f, 0.f, 0.f, 0.f);
    #pragma unroll
    for (int s = 0; s < S_SPLIT; s++) {
      float4 p = *(const float4*)(g_po + ((size_t)s * ROWS + r) * DD + i * 4);
      acc.x += p.x * w[s]; acc.y += p.y * w[s];
      acc.z += p.z * w[s]; acc.w += p.w * w[s];
    }
    acc.x *= inv; acc.y *= inv; acc.z *= inv; acc.w *= inv;
    *(float4*)(out + (size_t)r * DD + i * 4) = acc;
  }
}

// ---------------------------------------------------------------------------
extern "C" void kernel_launch(void* const* d_in, const int* in_sizes, int n_in,
                              void* d_out, int out_size)
{
  const float* x  = (const float*)d_in[0];
  const float* Wk = (const float*)d_in[1];
  const float* Wq = (const float*)d_in[2];
  const float* Wv = (const float*)d_in[3];
  float* out = (float*)d_out;

  proj_kernel<<<dim3(ROWS / 128, 3), 128>>>(x, Wk, Wq, Wv);
  attn_kernel<<<dim3(TT / QB, BB, S_SPLIT), 256>>>();
  combine_kernel<<<ROWS / 256, 256>>>(out);
}

// round 7
// speedup vs baseline: 2.2592x; 1.3562x over previous
#include <cuda_runtime.h>
#include <cuda_bf16.h>
#include <cstdint>

// Problem dims (fixed by reference)
#define BB 8
#define TT 2048
#define CC 1024
#define DD 64
#define ROWS (BB*TT)      // 16384
#define S_SPLIT 4
#define QB 128
#define KT 32
#define NEG_BIG  (-1.0e30f)
#define MASK_S   (-3.0e38f)

#define NTOT 192          // fused output cols: 64 K | 64 Q | 64 V
#define KC 32             // K-chunk per pipeline stage
#define NCHUNK (CC/KC)    // 32

// smem layout per stage (bf16, padded rows: 40 elems = 80B stride)
#define XPITCH 80
#define WPITCH 80
#define XH_BYTES (128*XPITCH)        // 10240
#define WH_BYTES (NTOT*WPITCH)       // 15360
#define STAGE_BYTES (2*XH_BYTES + 2*WH_BYTES)   // 51200
#define SMEM_REQ (2*STAGE_BYTES)                // 102400

// Scratch (allocation-free: __device__ globals)
__device__ float g_q[ROWS*DD];
__device__ float g_k[ROWS*DD];
__device__ float g_v[ROWS*DD];
__device__ float g_po[S_SPLIT*ROWS*DD];
__device__ float g_pm[S_SPLIT*ROWS];
__device__ float g_pl[S_SPLIT*ROWS];
__device__ __nv_bfloat16 g_wthi[NTOT*CC];   // W^T split hi, [n][k]
__device__ __nv_bfloat16 g_wtlo[NTOT*CC];   // W^T split lo

typedef unsigned long long u64;

__device__ __forceinline__ u64 pack2(float lo, float hi){
  u64 r; asm("mov.b64 %0,{%1,%2};" : "=l"(r) : "f"(lo), "f"(hi)); return r;
}
__device__ __forceinline__ void unpack2(u64 v, float &lo, float &hi){
  asm("mov.b64 {%0,%1},%2;" : "=f"(lo), "=f"(hi) : "l"(v));
}
__device__ __forceinline__ u64 ffma2(u64 a, u64 b, u64 c){
  u64 d; asm("fma.rn.f32x2 %0,%1,%2,%3;" : "=l"(d) : "l"(a), "l"(b), "l"(c)); return d;
}
__device__ __forceinline__ u64 fmul2(u64 a, u64 b){
  u64 d; asm("mul.rn.f32x2 %0,%1,%2;" : "=l"(d) : "l"(a), "l"(b)); return d;
}
__device__ __forceinline__ u64 fadd2(u64 a, u64 b){
  u64 d; asm("add.rn.f32x2 %0,%1,%2;" : "=l"(d) : "l"(a), "l"(b)); return d;
}
__device__ __forceinline__ void cpasync16(void* s, const void* g){
  uint32_t sa = (uint32_t)__cvta_generic_to_shared(s);
  asm volatile("cp.async.cg.shared.global [%0], [%1], 16;\n" :: "r"(sa), "l"(g) : "memory");
}
__device__ __forceinline__ void cpasync16u(uint32_t sa, const void* g){
  asm volatile("cp.async.cg.shared.global [%0], [%1], 16;\n" :: "r"(sa), "l"(g) : "memory");
}
__device__ __forceinline__ void cp_commit(){ asm volatile("cp.async.commit_group;\n" ::: "memory"); }
__device__ __forceinline__ void cp_wait0(){ asm volatile("cp.async.wait_group 0;\n" ::: "memory"); }

__device__ __forceinline__ uint32_t smem_u32(const void* p){
  return (uint32_t)__cvta_generic_to_shared(p);
}
__device__ __forceinline__ void ldm4(uint32_t* r, uint32_t addr){
  asm volatile("ldmatrix.sync.aligned.m8n8.x4.shared.b16 {%0,%1,%2,%3},[%4];"
    : "=r"(r[0]), "=r"(r[1]), "=r"(r[2]), "=r"(r[3]) : "r"(addr));
}
__device__ __forceinline__ void mma16816(float* d, const uint32_t* a,
                                         uint32_t b0, uint32_t b1){
  asm volatile("mma.sync.aligned.m16n8k16.row.col.f32.bf16.bf16.f32 "
    "{%0,%1,%2,%3},{%4,%5,%6,%7},{%8,%9},{%0,%1,%2,%3};"
    : "+f"(d[0]), "+f"(d[1]), "+f"(d[2]), "+f"(d[3])
    : "r"(a[0]), "r"(a[1]), "r"(a[2]), "r"(a[3]), "r"(b0), "r"(b1));
}

// ---------------------------------------------------------------------------
// Kernel 0: split W (fp32) into bf16 hi/lo, transposed to [n][k] K-major.
// ---------------------------------------------------------------------------
__global__ __launch_bounds__(256) void prep_w(
    const float* __restrict__ Wk, const float* __restrict__ Wq,
    const float* __restrict__ Wv)
{
  int n = blockIdx.x;
  const float* W = (n < 64) ? Wk : ((n < 128) ? Wq : Wv);
  int col = n & 63;
  for (int k = threadIdx.x; k < CC; k += 256) {
    float w = W[(size_t)k * DD + col];
    __nv_bfloat16 h = __float2bfloat16(w);
    float hf = __bfloat162float(h);
    __nv_bfloat16 l = __float2bfloat16(w - hf);
    g_wthi[n * CC + k] = h;
    g_wtlo[n * CC + k] = l;
  }
}

// ---------------------------------------------------------------------------
// Kernel 1: QKV projection via mma.sync bf16 (3-term precision split).
// grid=(ROWS/128), 256 threads (8 warps). CTA tile 128x192, warp tile 32x96.
// K in chunks of 32 (2 k16 steps), double-buffered smem, cp.async W halves,
// inline x->bf16 hi/lo conversion.
// ---------------------------------------------------------------------------
extern __shared__ char dsmem[];

__global__ __launch_bounds__(256) void proj_mma(const float* __restrict__ x)
{
  const int tid  = threadIdx.x;
  const int wid  = tid >> 5;
  const int lane = tid & 31;
  const int rowBase = blockIdx.x * 128;

  const uint32_t sbase = smem_u32(dsmem);
  // per-stage bases
  auto xhiB = [&](int st){ return sbase + (uint32_t)st * STAGE_BYTES; };
  auto xloB = [&](int st){ return xhiB(st) + XH_BYTES; };
  auto whiB = [&](int st){ return xhiB(st) + 2 * XH_BYTES; };
  auto wloB = [&](int st){ return whiB(st) + WH_BYTES; };

  const int wm = (wid & 3) * 32;     // warp row base in CTA tile
  const int wn = (wid >> 2) * 96;    // warp col base

  // ldmatrix per-thread offsets
  // A (m16k16): lanes 0-7 t0(m0-7,k0-7), 8-15 t1(m8-15,k0-7),
  //             16-23 t2(m0-7,k8-15), 24-31 t3(m8-15,k8-15)
  const int aRow = wm + ((lane >> 3) & 1) * 8 + (lane & 7);
  const int aK   = (lane >> 4) * 8;
  const uint32_t aOff = (uint32_t)(aRow * XPITCH + aK * 2);
  // B (k16n8 pair): lanes 0-7 (n0-7,k0-7), 8-15 (n0-7,k8-15),
  //                 16-23 (n8-15,k0-7), 24-31 (n8-15,k8-15)
  const int bN = wn + ((lane >> 4) & 1) * 8 + (lane & 7);
  const int bK = ((lane >> 3) & 1) * 8;
  const uint32_t bOff = (uint32_t)(bN * WPITCH + bK * 2);

  float d[2][12][4];
  #pragma unroll
  for (int mf = 0; mf < 2; mf++)
    #pragma unroll
    for (int nf = 0; nf < 12; nf++)
      #pragma unroll
      for (int c = 0; c < 4; c++) d[mf][nf][c] = 0.f;

  float4 xr[4];
  auto loadX = [&](int chunk) {
    const int k0 = chunk * KC;
    #pragma unroll
    for (int i = 0; i < 4; i++) {
      int f = i * 256 + tid;            // 0..1023 float4 units
      int row = f >> 3, kc = (f & 7) * 4;
      xr[i] = *(const float4*)(x + (size_t)(rowBase + row) * CC + k0 + kc);
    }
  };
  auto convertX = [&](int st) {
    const uint32_t xh = xhiB(st), xl = xloB(st);
    #pragma unroll
    for (int i = 0; i < 4; i++) {
      int f = i * 256 + tid;
      int row = f >> 3;
      uint32_t boff = (uint32_t)(row * XPITCH + (f & 7) * 8);
      float4 v = xr[i];
      uint32_t h01, h23, l01, l23;
      asm("cvt.rn.bf16x2.f32 %0, %1, %2;" : "=r"(h01) : "f"(v.y), "f"(v.x));
      asm("cvt.rn.bf16x2.f32 %0, %1, %2;" : "=r"(h23) : "f"(v.w), "f"(v.z));
      float f0 = __uint_as_float(h01 << 16);
      float f1 = __uint_as_float(h01 & 0xffff0000u);
      float f2 = __uint_as_float(h23 << 16);
      float f3 = __uint_as_float(h23 & 0xffff0000u);
      asm("cvt.rn.bf16x2.f32 %0, %1, %2;" : "=r"(l01) : "f"(v.y - f1), "f"(v.x - f0));
      asm("cvt.rn.bf16x2.f32 %0, %1, %2;" : "=r"(l23) : "f"(v.w - f3), "f"(v.z - f2));
      asm volatile("st.shared.v2.b32 [%0], {%1,%2};" :: "r"(xh + boff), "r"(h01), "r"(h23) : "memory");
      asm volatile("st.shared.v2.b32 [%0], {%1,%2};" :: "r"(xl + boff), "r"(l01), "r"(l23) : "memory");
    }
  };
  auto issueW = [&](int chunk, int st) {
    const int k0 = chunk * KC;
    const uint32_t wh = whiB(st), wl = wloB(st);
    #pragma unroll
    for (int i = 0; i < 6; i++) {
      int gid = i * 256 + tid;             // 0..1535
      int half = (gid >= 768) ? 1 : 0;
      int g2 = gid - half * 768;
      int n = g2 >> 2, c = g2 & 3;         // 4 x 16B per row
      const __nv_bfloat16* src =
          (half ? g_wtlo : g_wthi) + (size_t)n * CC + k0 + c * 8;
      uint32_t dst = (half ? wl : wh) + (uint32_t)(n * WPITCH + c * 16);
      cpasync16u(dst, src);
    }
    cp_commit();
  };

  // ---- prologue ----
  loadX(0);
  issueW(0, 0);
  convertX(0);
  loadX(1);

  for (int it = 0; it < NCHUNK; it++) {
    const int cur = it & 1;
    cp_wait0();
    __syncthreads();                 // W(it) arrived; x(it) converted; nxt free
    if (it + 1 < NCHUNK) issueW(it + 1, cur ^ 1);

    // ---- compute on stage cur: 2 k16 steps ----
    #pragma unroll
    for (int ks = 0; ks < 2; ks++) {
      uint32_t ahi[2][4], alo[2][4];
      #pragma unroll
      for (int mf = 0; mf < 2; mf++) {
        ldm4(ahi[mf], xhiB(cur) + aOff + (uint32_t)(mf * 16 * XPITCH + ks * 32));
        ldm4(alo[mf], xloB(cur) + aOff + (uint32_t)(mf * 16 * XPITCH + ks * 32));
      }
      #pragma unroll
      for (int nf2 = 0; nf2 < 6; nf2++) {
        uint32_t bhi[4], blo[4];
        ldm4(bhi, whiB(cur) + bOff + (uint32_t)(nf2 * 16 * WPITCH + ks * 32));
        ldm4(blo, wloB(cur) + bOff + (uint32_t)(nf2 * 16 * WPITCH + ks * 32));
        #pragma unroll
        for (int mf = 0; mf < 2; mf++) {
          #pragma unroll
          for (int s = 0; s < 2; s++) {
            float* dd = d[mf][2 * nf2 + s];
            mma16816(dd, ahi[mf], bhi[2 * s], bhi[2 * s + 1]);
            mma16816(dd, ahi[mf], blo[2 * s], blo[2 * s + 1]);
            mma16816(dd, alo[mf], bhi[2 * s], bhi[2 * s + 1]);
          }
        }
      }
    }

    if (it + 1 < NCHUNK) convertX(cur ^ 1);   // xr holds chunk it+1
    if (it + 2 < NCHUNK) loadX(it + 2);
  }

  // ---- epilogue: registers -> gmem ----
  // d frag: c0,c1 at (row=l/4, col=2*(l%4)+{0,1}); c2,c3 at row+8
  const int erow = lane >> 2;
  const int ecol = (lane & 3) * 2;
  #pragma unroll
  for (int mf = 0; mf < 2; mf++) {
    #pragma unroll
    for (int nf = 0; nf < 12; nf++) {
      int n0 = wn + nf * 8;
      int part = n0 >> 6;
      float* outp = (part == 0) ? g_k : ((part == 1) ? g_q : g_v);
      int col = (n0 & 63) + ecol;
      size_t r0 = (size_t)(rowBase + wm + mf * 16 + erow);
      *(float2*)(outp + r0 * DD + col)       = make_float2(d[mf][nf][0], d[mf][nf][1]);
      *(float2*)(outp + (r0 + 8) * DD + col) = make_float2(d[mf][nf][2], d[mf][nf][3]);
    }
  }
}

// ---------------------------------------------------------------------------
// Kernel 2: flash attention (R5: interleaved D-split-2, bulk 16-key softmax,
// cp.async double buffering). grid = (TT/QB, BB, S_SPLIT), 256 threads.
// ---------------------------------------------------------------------------
__global__ __launch_bounds__(256, 2) void attn_kernel()
{
  __shared__ float ks[2][KT * DD];
  __shared__ float vs[2][KT * DD];

  const int qb  = blockIdx.x;
  const int b   = blockIdx.y;
  const int sp  = blockIdx.z;
  const int tid = threadIdx.x;
  const int qi   = tid >> 1;
  const int half = tid & 1;

  const int t   = qb * QB + qi;
  const int row = b * TT + t;

  const int ntiles = qb + 1;
  const int ks0 = sp * ntiles * KT;

  auto issue_tile = [&](int it, int stage) {
    const int kt = ks0 + it * KT;
    #pragma unroll
    for (int r = 0; r < 2; r++) {
      int idx = tid + r * 256;
      int kr  = idx >> 4;
      int kc  = (idx & 15) << 2;
      size_t g = ((size_t)(b * TT + kt + kr)) * DD + kc;
      cpasync16(&ks[stage][kr * DD + kc], g_k + g);
      cpasync16(&vs[stage][kr * DD + kc], g_v + g);
    }
    cp_commit();
  };

  issue_tile(0, 0);

  u64 q2[16];
  {
    const float* qp = g_q + (size_t)row * DD + 4 * half;
    #pragma unroll
    for (int i = 0; i < 8; i++) {
      float4 v4 = *(const float4*)(qp + 8 * i);
      q2[2 * i]     = pack2(v4.x * 0.125f, v4.y * 0.125f);
      q2[2 * i + 1] = pack2(v4.z * 0.125f, v4.w * 0.125f);
    }
  }

  u64 o2[16];
  #pragma unroll
  for (int i = 0; i < 16; i++) o2[i] = pack2(0.f, 0.f);
  float m = NEG_BIG;
  float l = 0.f;

  for (int it = 0; it < ntiles; it++) {
    const int cur = it & 1;
    cp_wait0();
    __syncthreads();
    if (it + 1 < ntiles) issue_tile(it + 1, cur ^ 1);

    const int kt = ks0 + it * KT;
    const float* kbase = &ks[cur][0];
    const float* vbase = &vs[cur][0];

    #pragma unroll
    for (int j0 = 0; j0 < KT; j0 += 16) {
      if (kt + j0 > t) continue;

      float s[16];
      #pragma unroll
      for (int j = 0; j < 16; j++) {
        const ulonglong2* kp =
            (const ulonglong2*)(kbase + (j0 + j) * DD + 4 * half);
        u64 z = pack2(0.f, 0.f);
        u64 d0 = z, d1 = z, d2 = z, d3 = z;
        #pragma unroll
        for (int i = 0; i < 8; i += 2) {
          ulonglong2 kcA = kp[2 * i];
          ulonglong2 kcB = kp[2 * i + 2];
          d0 = ffma2(q2[2 * i],     kcA.x, d0);
          d1 = ffma2(q2[2 * i + 1], kcA.y, d1);
          d2 = ffma2(q2[2 * i + 2], kcB.x, d2);
          d3 = ffma2(q2[2 * i + 3], kcB.y, d3);
        }
        u64 rr = fadd2(fadd2(d0, d2), fadd2(d1, d3));
        float lo, hi; unpack2(rr, lo, hi);
        float sh = lo + hi;
        float sf = sh + __shfl_xor_sync(0xffffffffu, sh, 1);
        s[j] = (kt + j0 + j <= t) ? sf : MASK_S;
      }

      float M = s[0];
      #pragma unroll
      for (int j = 1; j < 16; j++) M = fmaxf(M, s[j]);
      float mn = fmaxf(m, M);
      float corr = __expf(m - mn);
      l *= corr;
      u64 cr = pack2(corr, corr);
      #pragma unroll
      for (int i = 0; i < 16; i++) o2[i] = fmul2(o2[i], cr);
      m = mn;

      float lsum = 0.f;
      #pragma unroll
      for (int j = 0; j < 16; j++) {
        float p = __expf(s[j] - m);
        lsum += p;
        u64 p2 = pack2(p, p);
        const ulonglong2* vp =
            (const ulonglong2*)(vbase + (j0 + j) * DD + 4 * half);
        #pragma unroll
        for (int i = 0; i < 8; i++) {
          ulonglong2 vv = vp[2 * i];
          o2[2 * i]     = ffma2(p2, vv.x, o2[2 * i]);
          o2[2 * i + 1] = ffma2(p2, vv.y, o2[2 * i + 1]);
        }
      }
      l += lsum;
    }
  }

  size_t pr = (size_t)sp * ROWS + row;
  if (half == 0) { g_pm[pr] = m; g_pl[pr] = l; }
  float* po = g_po + pr * (size_t)DD + 4 * half;
  #pragma unroll
  for (int i = 0; i < 8; i++) {
    *(ulonglong2*)(po + 8 * i) = make_ulonglong2(o2[2 * i], o2[2 * i + 1]);
  }
}

// ---------------------------------------------------------------------------
// Kernel 3: LSE combine across splits + final normalization.
// ---------------------------------------------------------------------------
__global__ __launch_bounds__(256) void combine_kernel(float* __restrict__ out)
{
  int r = blockIdx.x * blockDim.x + threadIdx.x;

  float m[S_SPLIT], l[S_SPLIT];
  #pragma unroll
  for (int s = 0; s < S_SPLIT; s++) {
    m[s] = g_pm[(size_t)s * ROWS + r];
    l[s] = g_pl[(size_t)s * ROWS + r];
  }
  float M = fmaxf(fmaxf(m[0], m[1]), fmaxf(m[2], m[3]));
  float w[S_SPLIT]; float L = 0.f;
  #pragma unroll
  for (int s = 0; s < S_SPLIT; s++) { w[s] = __expf(m[s] - M); L += l[s] * w[s]; }
  float inv = 1.0f / L;

  #pragma unroll
  for (int i = 0; i < 16; i++) {
    float4 acc = make_float4(0.f, 0.f, 0.f, 0.f);
    #pragma unroll
    for (int s = 0; s < S_SPLIT; s++) {
      float4 p = *(const float4*)(g_po + ((size_t)s * ROWS + r) * DD + i * 4);
      acc.x += p.x * w[s]; acc.y += p.y * w[s];
      acc.z += p.z * w[s]; acc.w += p.w * w[s];
    }
    acc.x *= inv; acc.y *= inv; acc.z *= inv; acc.w *= inv;
    *(float4*)(out + (size_t)r * DD + i * 4) = acc;
  }
}

// ---------------------------------------------------------------------------
extern "C" void kernel_launch(void* const* d_in, const int* in_sizes, int n_in,
                              void* d_out, int out_size)
{
  const float* x  = (const float*)d_in[0];
  const float* Wk = (const float*)d_in[1];
  const float* Wq = (const float*)d_in[2];
  const float* Wv = (const float*)d_in[3];
  float* out = (float*)d_out;

  cudaFuncSetAttribute(proj_mma, cudaFuncAttributeMaxDynamicSharedMemorySize, SMEM_REQ);

  prep_w<<<NTOT, 256>>>(Wk, Wq, Wv);
  proj_mma<<<ROWS / 128, 256, SMEM_REQ>>>(x);
  attn_kernel<<<dim3(TT / QB, BB, S_SPLIT), 256>>>();
  combine_kernel<<<ROWS / 256, 256>>>(out);
}

// round 8
// speedup vs baseline: 4.5504x; 2.0141x over previous
#include <cuda_runtime.h>
#include <cuda_bf16.h>
#include <cstdint>

// Problem dims (fixed by reference)
#define BB 8
#define TT 2048
#define CC 1024
#define DD 64
#define ROWS (BB*TT)      // 16384
#define S_SPLIT 4
#define NEG_BIG  (-1.0e30f)
#define MASK_S   (-3.0e38f)

#define NTOT 192          // fused proj cols: 64 K | 64 Q | 64 V
#define KC 32
#define NCHUNK (CC/KC)    // 32

// proj smem (bf16, padded rows: 40 elems = 80B stride)
#define XPITCH 80
#define WPITCH 80
#define XH_BYTES (128*XPITCH)
#define WH_BYTES (NTOT*WPITCH)
#define STAGE_BYTES (2*XH_BYTES + 2*WH_BYTES)
#define SMEM_PROJ (2*STAGE_BYTES)

// attn smem: bf16 pitch 72 elems = 144B (odd 16B multiple -> conflict-free LDSM)
#define APITCH 144
#define Q_BYTES (128*APITCH)        // 18432 per array
#define KV_ARR  (64*APITCH)         // 9216 per array
#define KV_STAGE (4*KV_ARR)         // 36864 (Khi,Klo,Vhi,Vlo)
#define SMEM_ATT (2*Q_BYTES + 2*KV_STAGE)   // 110592

// Scratch (allocation-free: __device__ globals)
__device__ float g_po[S_SPLIT*ROWS*DD];
__device__ float g_pm[S_SPLIT*ROWS];
__device__ float g_pl[S_SPLIT*ROWS];
__device__ __nv_bfloat16 g_wthi[NTOT*CC];
__device__ __nv_bfloat16 g_wtlo[NTOT*CC];
__device__ __nv_bfloat16 g_qhi[ROWS*DD], g_qlo[ROWS*DD];
__device__ __nv_bfloat16 g_khi[ROWS*DD], g_klo[ROWS*DD];
__device__ __nv_bfloat16 g_vhi[ROWS*DD], g_vlo[ROWS*DD];

__device__ __forceinline__ void cpasync16u(uint32_t sa, const void* g){
  asm volatile("cp.async.cg.shared.global [%0], [%1], 16;\n" :: "r"(sa), "l"(g) : "memory");
}
__device__ __forceinline__ void cp_commit(){ asm volatile("cp.async.commit_group;\n" ::: "memory"); }
__device__ __forceinline__ void cp_wait0(){ asm volatile("cp.async.wait_group 0;\n" ::: "memory"); }
__device__ __forceinline__ void cp_wait1(){ asm volatile("cp.async.wait_group 1;\n" ::: "memory"); }

__device__ __forceinline__ uint32_t smem_u32(const void* p){
  return (uint32_t)__cvta_generic_to_shared(p);
}
__device__ __forceinline__ void ldm4(uint32_t* r, uint32_t addr){
  asm volatile("ldmatrix.sync.aligned.m8n8.x4.shared.b16 {%0,%1,%2,%3},[%4];"
    : "=r"(r[0]), "=r"(r[1]), "=r"(r[2]), "=r"(r[3]) : "r"(addr));
}
__device__ __forceinline__ void ldm4t(uint32_t* r, uint32_t addr){
  asm volatile("ldmatrix.sync.aligned.m8n8.x4.trans.shared.b16 {%0,%1,%2,%3},[%4];"
    : "=r"(r[0]), "=r"(r[1]), "=r"(r[2]), "=r"(r[3]) : "r"(addr));
}
__device__ __forceinline__ void mma16816(float* d, const uint32_t* a,
                                         uint32_t b0, uint32_t b1){
  asm volatile("mma.sync.aligned.m16n8k16.row.col.f32.bf16.bf16.f32 "
    "{%0,%1,%2,%3},{%4,%5,%6,%7},{%8,%9},{%0,%1,%2,%3};"
    : "+f"(d[0]), "+f"(d[1]), "+f"(d[2]), "+f"(d[3])
    : "r"(a[0]), "r"(a[1]), "r"(a[2]), "r"(a[3]), "r"(b0), "r"(b1));
}
// pack (a -> low half, b -> high half) with exact fp32 residual in lo
__device__ __forceinline__ void bf16split2(float a, float b, uint32_t &hi, uint32_t &lo){
  asm("cvt.rn.bf16x2.f32 %0, %1, %2;" : "=r"(hi) : "f"(b), "f"(a));
  float fa = __uint_as_float(hi << 16);
  float fb = __uint_as_float(hi & 0xffff0000u);
  asm("cvt.rn.bf16x2.f32 %0, %1, %2;" : "=r"(lo) : "f"(b - fb), "f"(a - fa));
}

// ---------------------------------------------------------------------------
// Kernel 0: split W into bf16 hi/lo, transposed [n][k].
// ---------------------------------------------------------------------------
__global__ __launch_bounds__(256) void prep_w(
    const float* __restrict__ Wk, const float* __restrict__ Wq,
    const float* __restrict__ Wv)
{
  int n = blockIdx.x;
  const float* W = (n < 64) ? Wk : ((n < 128) ? Wq : Wv);
  int col = n & 63;
  for (int k = threadIdx.x; k < CC; k += 256) {
    float w = W[(size_t)k * DD + col];
    __nv_bfloat16 h = __float2bfloat16(w);
    __nv_bfloat16 l = __float2bfloat16(w - __bfloat162float(h));
    g_wthi[n * CC + k] = h;
    g_wtlo[n * CC + k] = l;
  }
}

// ---------------------------------------------------------------------------
// Kernel 1: QKV projection via mma.sync (3-term split). Epilogue writes
// bf16 hi/lo Q(pre-scaled 0.125)/K/V for the attention kernel.
// ---------------------------------------------------------------------------
extern __shared__ char dsmem[];

__global__ __launch_bounds__(256) void proj_mma(const float* __restrict__ x)
{
  const int tid  = threadIdx.x;
  const int wid  = tid >> 5;
  const int lane = tid & 31;
  const int rowBase = blockIdx.x * 128;

  const uint32_t sbase = smem_u32(dsmem);
  auto xhiB = [&](int st){ return sbase + (uint32_t)st * STAGE_BYTES; };
  auto xloB = [&](int st){ return xhiB(st) + XH_BYTES; };
  auto whiB = [&](int st){ return xhiB(st) + 2 * XH_BYTES; };
  auto wloB = [&](int st){ return whiB(st) + WH_BYTES; };

  const int wm = (wid & 3) * 32;
  const int wn = (wid >> 2) * 96;

  const int aRow = wm + ((lane >> 3) & 1) * 8 + (lane & 7);
  const int aK   = (lane >> 4) * 8;
  const uint32_t aOff = (uint32_t)(aRow * XPITCH + aK * 2);
  const int bN = wn + ((lane >> 4) & 1) * 8 + (lane & 7);
  const int bK = ((lane >> 3) & 1) * 8;
  const uint32_t bOff = (uint32_t)(bN * WPITCH + bK * 2);

  float d[2][12][4];
  #pragma unroll
  for (int mf = 0; mf < 2; mf++)
    #pragma unroll
    for (int nf = 0; nf < 12; nf++)
      #pragma unroll
      for (int c = 0; c < 4; c++) d[mf][nf][c] = 0.f;

  float4 xr[4];
  auto loadX = [&](int chunk) {
    const int k0 = chunk * KC;
    #pragma unroll
    for (int i = 0; i < 4; i++) {
      int f = i * 256 + tid;
      int row = f >> 3, kc = (f & 7) * 4;
      xr[i] = *(const float4*)(x + (size_t)(rowBase + row) * CC + k0 + kc);
    }
  };
  auto convertX = [&](int st) {
    const uint32_t xh = xhiB(st), xl = xloB(st);
    #pragma unroll
    for (int i = 0; i < 4; i++) {
      int f = i * 256 + tid;
      int row = f >> 3;
      uint32_t boff = (uint32_t)(row * XPITCH + (f & 7) * 8);
      float4 v = xr[i];
      uint32_t h01, h23, l01, l23;
      bf16split2(v.x, v.y, h01, l01);
      bf16split2(v.z, v.w, h23, l23);
      asm volatile("st.shared.v2.b32 [%0], {%1,%2};" :: "r"(xh + boff), "r"(h01), "r"(h23) : "memory");
      asm volatile("st.shared.v2.b32 [%0], {%1,%2};" :: "r"(xl + boff), "r"(l01), "r"(l23) : "memory");
    }
  };
  auto issueW = [&](int chunk, int st) {
    const int k0 = chunk * KC;
    const uint32_t wh = whiB(st), wl = wloB(st);
    #pragma unroll
    for (int i = 0; i < 6; i++) {
      int gid = i * 256 + tid;
      int half = (gid >= 768) ? 1 : 0;
      int g2 = gid - half * 768;
      int n = g2 >> 2, c = g2 & 3;
      const __nv_bfloat16* src =
          (half ? g_wtlo : g_wthi) + (size_t)n * CC + k0 + c * 8;
      uint32_t dst = (half ? wl : wh) + (uint32_t)(n * WPITCH + c * 16);
      cpasync16u(dst, src);
    }
    cp_commit();
  };

  loadX(0);
  issueW(0, 0);
  convertX(0);
  loadX(1);

  for (int it = 0; it < NCHUNK; it++) {
    const int cur = it & 1;
    cp_wait0();
    __syncthreads();
    if (it + 1 < NCHUNK) issueW(it + 1, cur ^ 1);

    #pragma unroll
    for (int ks = 0; ks < 2; ks++) {
      uint32_t ahi[2][4], alo[2][4];
      #pragma unroll
      for (int mf = 0; mf < 2; mf++) {
        ldm4(ahi[mf], xhiB(cur) + aOff + (uint32_t)(mf * 16 * XPITCH + ks * 32));
        ldm4(alo[mf], xloB(cur) + aOff + (uint32_t)(mf * 16 * XPITCH + ks * 32));
      }
      #pragma unroll
      for (int nf2 = 0; nf2 < 6; nf2++) {
        uint32_t bhi[4], blo[4];
        ldm4(bhi, whiB(cur) + bOff + (uint32_t)(nf2 * 16 * WPITCH + ks * 32));
        ldm4(blo, wloB(cur) + bOff + (uint32_t)(nf2 * 16 * WPITCH + ks * 32));
        #pragma unroll
        for (int mf = 0; mf < 2; mf++) {
          #pragma unroll
          for (int s = 0; s < 2; s++) {
            float* dd = d[mf][2 * nf2 + s];
            mma16816(dd, ahi[mf], bhi[2 * s], bhi[2 * s + 1]);
            mma16816(dd, ahi[mf], blo[2 * s], blo[2 * s + 1]);
            mma16816(dd, alo[mf], bhi[2 * s], bhi[2 * s + 1]);
          }
        }
      }
    }

    if (it + 1 < NCHUNK) convertX(cur ^ 1);
    if (it + 2 < NCHUNK) loadX(it + 2);
  }

  // epilogue: split fp32 results to bf16 hi/lo gmem (Q scaled by 0.125)
  const int erow = lane >> 2;
  const int ecol = (lane & 3) * 2;
  #pragma unroll
  for (int mf = 0; mf < 2; mf++) {
    #pragma unroll
    for (int nf = 0; nf < 12; nf++) {
      int n0 = wn + nf * 8;
      int part = n0 >> 6;
      __nv_bfloat16* hp = (part == 0) ? g_khi : ((part == 1) ? g_qhi : g_vhi);
      __nv_bfloat16* lp = (part == 0) ? g_klo : ((part == 1) ? g_qlo : g_vlo);
      float sc = (part == 1) ? 0.125f : 1.0f;
      int col = (n0 & 63) + ecol;
      size_t r0 = (size_t)(rowBase + wm + mf * 16 + erow);
      uint32_t h, l2;
      bf16split2(d[mf][nf][0] * sc, d[mf][nf][1] * sc, h, l2);
      *(uint32_t*)(hp + r0 * DD + col) = h;
      *(uint32_t*)(lp + r0 * DD + col) = l2;
      bf16split2(d[mf][nf][2] * sc, d[mf][nf][3] * sc, h, l2);
      *(uint32_t*)(hp + (r0 + 8) * DD + col) = h;
      *(uint32_t*)(lp + (r0 + 8) * DD + col) = l2;
    }
  }
}

// ---------------------------------------------------------------------------
// Kernel 2: FlashAttention-2 on mma.sync. grid=(16, BB, 4), 256 thr (8 warps,
// m16 each). Strided split-KV (tile j -> split j%4). 3-term bf16 split for
// both QK^T and PV. Double-buffered cp.async K/V hi/lo tiles.
// ---------------------------------------------------------------------------
__global__ __launch_bounds__(256) void attn_mma()
{
  const int qb  = blockIdx.x;          // 0..15  (128 queries each)
  const int b   = blockIdx.y;
  const int sp  = blockIdx.z;
  const int tid = threadIdx.x;
  const int wid = tid >> 5;
  const int lane = tid & 31;

  const int ntt = 2 * (qb + 1);        // total 64-key tiles for this q-block
  const int nt  = (ntt > sp) ? (ntt - sp + 3) / 4 : 0;

  float o[8][4];
  #pragma unroll
  for (int nf = 0; nf < 8; nf++)
    #pragma unroll
    for (int c = 0; c < 4; c++) o[nf][c] = 0.f;
  float m0 = NEG_BIG, m1 = NEG_BIG, l0 = 0.f, l1 = 0.f;

  const int erow = lane >> 2;
  const int ecol = (lane & 3) * 2;
  const int row0g = b * TT + qb * 128 + wid * 16 + erow;   // global row (lo)

  if (nt == 0) goto epilogue;

  {
    const uint32_t sb  = smem_u32(dsmem);
    const uint32_t QHI = sb, QLO = sb + Q_BYTES;
    const uint32_t KVB = sb + 2 * Q_BYTES;

    // ---- stage Q (group 0) ----
    {
      const int rbase = b * TT + qb * 128;
      #pragma unroll
      for (int i = 0; i < 8; i++) {
        int gid = i * 256 + tid;               // 0..2047
        int arr = gid >> 10;                   // 0=hi,1=lo
        int g2 = gid & 1023;
        int row = g2 >> 3, ch = g2 & 7;
        const __nv_bfloat16* src = (arr ? g_qlo : g_qhi) + (size_t)(rbase + row) * DD + ch * 8;
        cpasync16u((arr ? QLO : QHI) + (uint32_t)(row * APITCH + ch * 16), src);
      }
      cp_commit();
    }

    auto issueKV = [&](int j, int st) {
      const int k0 = j * 64;
      const uint32_t base = KVB + (uint32_t)st * KV_STAGE;
      #pragma unroll
      for (int i = 0; i < 8; i++) {
        int gid = i * 256 + tid;               // 0..2047
        int arr = gid >> 9;                    // 0=Khi,1=Klo,2=Vhi,3=Vlo
        int g2 = gid & 511;
        int row = g2 >> 3, ch = g2 & 7;
        const __nv_bfloat16* ap =
            (arr == 0) ? g_khi : (arr == 1) ? g_klo : (arr == 2) ? g_vhi : g_vlo;
        const __nv_bfloat16* src = ap + (size_t)(b * TT + k0 + row) * DD + ch * 8;
        cpasync16u(base + (uint32_t)(arr * KV_ARR + row * APITCH + ch * 16), src);
      }
      cp_commit();
    };

    issueKV(sp, 0);          // group 1
    cp_wait1();              // Q (group 0) done
    __syncthreads();

    // ---- Q fragments (register-resident) ----
    const uint32_t qoff = (uint32_t)((wid * 16 + (lane & 15)) * APITCH + (lane >> 4) * 16);
    uint32_t qh[4][4], ql[4][4];
    #pragma unroll
    for (int ks = 0; ks < 4; ks++) {
      ldm4(qh[ks], QHI + qoff + ks * 32);
      ldm4(ql[ks], QLO + qoff + ks * 32);
    }

    const uint32_t koff = (uint32_t)((((lane >> 4) & 1) * 8 + (lane & 7)) * APITCH + ((lane >> 3) & 1) * 16);
    const uint32_t voff = (uint32_t)((((lane >> 3) & 1) * 8 + (lane & 7)) * APITCH + ((lane >> 4) & 1) * 16);

    for (int tix = 0; tix < nt; tix++) {
      const int j  = sp + tix * 4;
      const int st = tix & 1;
      const int k0 = j * 64;
      cp_wait0();
      __syncthreads();
      if (tix + 1 < nt) issueKV(sp + (tix + 1) * 4, st ^ 1);

      const uint32_t stage = KVB + (uint32_t)st * KV_STAGE;
      const uint32_t KH = stage, KL = stage + KV_ARR;
      const uint32_t VH = stage + 2 * KV_ARR, VL = stage + 3 * KV_ARR;

      // ---- S = Q K^T (3 terms) ----
      float s[8][4];
      #pragma unroll
      for (int nf = 0; nf < 8; nf++)
        #pragma unroll
        for (int c = 0; c < 4; c++) s[nf][c] = 0.f;

      #pragma unroll
      for (int ks = 0; ks < 4; ks++) {
        #pragma unroll
        for (int g = 0; g < 4; g++) {
          uint32_t bh[4], bl[4];
          uint32_t off = koff + (uint32_t)(g * 16 * APITCH + ks * 32);
          ldm4(bh, KH + off);
          ldm4(bl, KL + off);
          mma16816(s[2*g],   qh[ks], bh[0], bh[1]);
          mma16816(s[2*g+1], qh[ks], bh[2], bh[3]);
          mma16816(s[2*g],   qh[ks], bl[0], bl[1]);
          mma16816(s[2*g+1], qh[ks], bl[2], bl[3]);
          mma16816(s[2*g],   ql[ks], bh[0], bh[1]);
          mma16816(s[2*g+1], ql[ks], bh[2], bh[3]);
        }
      }

      // ---- causal mask (only the last two tiles need it) ----
      if (k0 + 63 > qb * 128) {
        const int rlo = qb * 128 + wid * 16 + erow;
        #pragma unroll
        for (int nf = 0; nf < 8; nf++) {
          int key = k0 + nf * 8 + ecol;
          if (key     > rlo)     s[nf][0] = MASK_S;
          if (key + 1 > rlo)     s[nf][1] = MASK_S;
          if (key     > rlo + 8) s[nf][2] = MASK_S;
          if (key + 1 > rlo + 8) s[nf][3] = MASK_S;
        }
      }

      // ---- online softmax (fragment rows: l/4 and l/4+8) ----
      float r0 = fmaxf(s[0][0], s[0][1]);
      float r1 = fmaxf(s[0][2], s[0][3]);
      #pragma unroll
      for (int nf = 1; nf < 8; nf++) {
        r0 = fmaxf(r0, fmaxf(s[nf][0], s[nf][1]));
        r1 = fmaxf(r1, fmaxf(s[nf][2], s[nf][3]));
      }
      r0 = fmaxf(r0, __shfl_xor_sync(0xffffffffu, r0, 1));
      r0 = fmaxf(r0, __shfl_xor_sync(0xffffffffu, r0, 2));
      r1 = fmaxf(r1, __shfl_xor_sync(0xffffffffu, r1, 1));
      r1 = fmaxf(r1, __shfl_xor_sync(0xffffffffu, r1, 2));
      float mn0 = fmaxf(m0, r0), mn1 = fmaxf(m1, r1);
      float cr0 = __expf(m0 - mn0), cr1 = __expf(m1 - mn1);
      l0 *= cr0; l1 *= cr1; m0 = mn0; m1 = mn1;
      #pragma unroll
      for (int nf = 0; nf < 8; nf++) {
        o[nf][0] *= cr0; o[nf][1] *= cr0;
        o[nf][2] *= cr1; o[nf][3] *= cr1;
      }

      // ---- exp, row sums, P -> A-frag bf16 hi/lo ----
      float sum0 = 0.f, sum1 = 0.f;
      uint32_t ph[4][4], pl4[4][4];
      #pragma unroll
      for (int nf = 0; nf < 8; nf++) {
        float p0 = __expf(s[nf][0] - m0);
        float p1 = __expf(s[nf][1] - m0);
        float p2 = __expf(s[nf][2] - m1);
        float p3 = __expf(s[nf][3] - m1);
        sum0 += p0 + p1; sum1 += p2 + p3;
        int kk = nf >> 1, bs = (nf & 1) * 2;
        bf16split2(p0, p1, ph[kk][bs],     pl4[kk][bs]);
        bf16split2(p2, p3, ph[kk][bs + 1], pl4[kk][bs + 1]);
      }
      sum0 += __shfl_xor_sync(0xffffffffu, sum0, 1);
      sum0 += __shfl_xor_sync(0xffffffffu, sum0, 2);
      sum1 += __shfl_xor_sync(0xffffffffu, sum1, 1);
      sum1 += __shfl_xor_sync(0xffffffffu, sum1, 2);
      l0 += sum0; l1 += sum1;

      // ---- O += P V (3 terms, V via trans-ldmatrix) ----
      #pragma unroll
      for (int kk = 0; kk < 4; kk++) {
        #pragma unroll
        for (int dg = 0; dg < 4; dg++) {
          uint32_t vh[4], vl[4];
          uint32_t off = voff + (uint32_t)(kk * 16 * APITCH + dg * 32);
          ldm4t(vh, VH + off);
          ldm4t(vl, VL + off);
          mma16816(o[2*dg],   ph[kk],  vh[0], vh[1]);
          mma16816(o[2*dg+1], ph[kk],  vh[2], vh[3]);
          mma16816(o[2*dg],   ph[kk],  vl[0], vl[1]);
          mma16816(o[2*dg+1], ph[kk],  vl[2], vl[3]);
          mma16816(o[2*dg],   pl4[kk], vh[0], vh[1]);
          mma16816(o[2*dg+1], pl4[kk], vh[2], vh[3]);
        }
      }
    }
  }

epilogue:
  {
    size_t pr0 = (size_t)sp * ROWS + row0g;
    size_t pr1 = pr0 + 8;
    if ((lane & 3) == 0) {
      g_pm[pr0] = m0; g_pl[pr0] = l0;
      g_pm[pr1] = m1; g_pl[pr1] = l1;
    }
    #pragma unroll
    for (int nf = 0; nf < 8; nf++) {
      int col = nf * 8 + ecol;
      *(float2*)(g_po + pr0 * DD + col) = make_float2(o[nf][0], o[nf][1]);
      *(float2*)(g_po + pr1 * DD + col) = make_float2(o[nf][2], o[nf][3]);
    }
  }
}

// ---------------------------------------------------------------------------
// Kernel 3: LSE combine. One thread per output float4. grid=1024.
// ---------------------------------------------------------------------------
__global__ __launch_bounds__(256) void combine_kernel(float* __restrict__ out)
{
  int gid = blockIdx.x * 256 + threadIdx.x;   // 0 .. ROWS*16-1
  int r  = gid >> 4;
  int c  = (gid & 15) * 4;

  float m[S_SPLIT], l[S_SPLIT];
  #pragma unroll
  for (int s = 0; s < S_SPLIT; s++) {
    m[s] = g_pm[(size_t)s * ROWS + r];
    l[s] = g_pl[(size_t)s * ROWS + r];
  }
  float M = fmaxf(fmaxf(m[0], m[1]), fmaxf(m[2], m[3]));
  float w[S_SPLIT]; float L = 0.f;
  #pragma unroll
  for (int s = 0; s < S_SPLIT; s++) { w[s] = __expf(m[s] - M); L += l[s] * w[s]; }
  float inv = 1.0f / L;

  float4 acc = make_float4(0.f, 0.f, 0.f, 0.f);
  #pragma unroll
  for (int s = 0; s < S_SPLIT; s++) {
    float4 p = *(const float4*)(g_po + ((size_t)s * ROWS + r) * DD + c);
    acc.x += p.x * w[s]; acc.y += p.y * w[s];
    acc.z += p.z * w[s]; acc.w += p.w * w[s];
  }
  acc.x *= inv; acc.y *= inv; acc.z *= inv; acc.w *= inv;
  *(float4*)(out + (size_t)r * DD + c) = acc;
}

// ---------------------------------------------------------------------------
extern "C" void kernel_launch(void* const* d_in, const int* in_sizes, int n_in,
                              void* d_out, int out_size)
{
  const float* x  = (const float*)d_in[0];
  const float* Wk = (const float*)d_in[1];
  const float* Wq = (const float*)d_in[2];
  const float* Wv = (const float*)d_in[3];
  float* out = (float*)d_out;

  cudaFuncSetAttribute(proj_mma, cudaFuncAttributeMaxDynamicSharedMemorySize, SMEM_PROJ);
  cudaFuncSetAttribute(attn_mma, cudaFuncAttributeMaxDynamicSharedMemorySize, SMEM_ATT);

  prep_w<<<NTOT, 256>>>(Wk, Wq, Wv);
  proj_mma<<<ROWS / 128, 256, SMEM_PROJ>>>(x);
  attn_mma<<<dim3(TT / 128, BB, S_SPLIT), 256, SMEM_ATT>>>();
  combine_kernel<<<ROWS * 16 / 256, 256>>>(out);
}